// round 2
// baseline (speedup 1.0000x reference)
#include <cuda_runtime.h>

// ---------------- problem constants ----------------
#define Bc   64
#define Tc   1024
#define Dc   1024
#define NB   128      // persistent blocks (<= 148 SMs, 1 block/SM)
#define NT   128      // threads per block
#define KT   32       // k-tile
#define PAD  36       // smem row pitch in floats (= 9 x 16B, conflict-free)
#define DPB  8        // d-columns owned per block (1024/128)
#define NKT  64       // 2048 / KT

// ---------------- persistent device state ----------------
__device__ __align__(256) float g_h0[2][Bc * Dc];
__device__ __align__(256) float g_h1[2][Bc * Dc];
__device__ __align__(256) float g_c0[Bc * Dc];
__device__ __align__(256) float g_c1[Bc * Dc];
__device__ unsigned g_bar_count = 0;
__device__ unsigned g_bar_gen   = 0;

// ---------------- small helpers ----------------
__device__ __forceinline__ void cpa16(unsigned dst, const void* src) {
    asm volatile("cp.async.cg.shared.global [%0], [%1], 16;" :: "r"(dst), "l"(src));
}
#define CP_COMMIT() asm volatile("cp.async.commit_group;")

// packed fp32x2 FMA: d += a*b on both lanes (PTX-only path on sm_103a)
#define FMA2(d, a, b) \
    asm("fma.rn.f32x2 %0, %1, %2, %0;" : "+l"(d) : "l"(a), "l"(b))

__device__ __forceinline__ float sigf(float x) {
    return 1.0f / (1.0f + __expf(-x));
}

// Self-resetting grid barrier (monotonic generation counter: safe across
// CUDA-graph replays; g_bar_count returns to 0 after every barrier).
__device__ __forceinline__ void grid_barrier() {
    __threadfence();            // make this block's global writes visible (L2)
    __syncthreads();
    if (threadIdx.x == 0) {
        unsigned gen = atomicAdd(&g_bar_gen, 0u);
        if (atomicAdd(&g_bar_count, 1u) == NB - 1) {
            atomicExch(&g_bar_count, 0u);
            __threadfence();
            atomicAdd(&g_bar_gen, 1u);
        } else {
            while (atomicAdd(&g_bar_gen, 0u) == gen) { __nanosleep(128); }
        }
    }
    __syncthreads();
}

// ---------------- tile prefetch (cp.async, L2-direct) ----------------
// A tile: [64 rows(batch) x KT k] ; W tile: [32 gate-cols x KT k]
// K = 2048 = [0,1024): (x or h0_new) with Wih ; [1024,2048): h_prev with Whh
__device__ __forceinline__ void load_tile(
    int kt, int buf,
    const float* __restrict__ Alo, long strideLo,
    const float* __restrict__ Ahi,
    const float* __restrict__ Wih, const float* __restrict__ Whh,
    int d0,
    float (&sA)[2][64 * PAD], float (&sW)[2][32 * PAD])
{
    const int k0 = kt * KT;
    const float* Asrc; long astr; const float* Wsrc; int kl;
    if (k0 < Dc) { Asrc = Alo; astr = strideLo; Wsrc = Wih; kl = k0; }
    else         { Asrc = Ahi; astr = Dc;       Wsrc = Whh; kl = k0 - Dc; }

    unsigned aB = (unsigned)__cvta_generic_to_shared(&sA[buf][0]);
    unsigned wB = (unsigned)__cvta_generic_to_shared(&sW[buf][0]);
    const int tid = threadIdx.x;

    // A: 64 rows x 32 floats = 512 x 16B chunks
#pragma unroll
    for (int i = 0; i < 4; i++) {
        int idx = tid + i * NT;
        int row = idx >> 3, kq = idx & 7;
        cpa16(aB + (unsigned)(row * PAD + kq * 4) * 4u,
              Asrc + (long)row * astr + kl + kq * 4);
    }
    // W: 32 cols x 32 floats = 256 x 16B chunks. col = gate*8 + dd
#pragma unroll
    for (int i = 0; i < 2; i++) {
        int idx = tid + i * NT;
        int col = idx >> 3, kq = idx & 7;
        int wr  = (col >> 3) * Dc + d0 + (col & 7);   // global gate row
        cpa16(wB + (unsigned)(col * PAD + kq * 4) * 4u,
              Wsrc + (long)wr * Dc + kl + kq * 4);
    }
    CP_COMMIT();
}

// ---------------- one LSTM cell step for this block's d-slice ----------------
// Computes gates[64 x 32cols] = [Alo|Ahi] @ W^T rows, then the cell update.
// Thread (tx=tid&7, ty=tid>>3): rows {16r+ty}, cols {8c+tx}  ->  gate c of d=d0+tx
__device__ __forceinline__ void do_layer(
    const float* __restrict__ Alo, long strideLo,
    const float* __restrict__ Ahi,
    const float* __restrict__ Wih, const float* __restrict__ Whh,
    float* __restrict__ cst, float* __restrict__ hnext,
    float* __restrict__ outp,            // null for layer0, out + t*D for layer1
    int d0,
    float (&sA)[2][64 * PAD], float (&sW)[2][32 * PAD])
{
    const int tid = threadIdx.x;
    const int tx = tid & 7;        // -> d offset (dd)
    const int ty = tid >> 3;       // -> batch row group

    // f32x2 accumulators: lane0 = even-k partial, lane1 = odd-k partial
    unsigned long long acc[4][4];
#pragma unroll
    for (int r = 0; r < 4; r++)
#pragma unroll
        for (int c = 0; c < 4; c++) acc[r][c] = 0ull;

    load_tile(0, 0, Alo, strideLo, Ahi, Wih, Whh, d0, sA, sW);

    for (int kt = 0; kt < NKT; kt++) {
        if (kt < NKT - 1) {
            load_tile(kt + 1, (kt + 1) & 1, Alo, strideLo, Ahi, Wih, Whh, d0, sA, sW);
            asm volatile("cp.async.wait_group 1;");
        } else {
            asm volatile("cp.async.wait_group 0;");
        }
        __syncthreads();

        const float* A = sA[kt & 1];
        const float* W = sW[kt & 1];
#pragma unroll
        for (int kk = 0; kk < KT; kk += 4) {
            ulonglong2 av[4], wv[4];
#pragma unroll
            for (int r = 0; r < 4; r++)
                av[r] = *reinterpret_cast<const ulonglong2*>(&A[(16 * r + ty) * PAD + kk]);
#pragma unroll
            for (int c = 0; c < 4; c++)
                wv[c] = *reinterpret_cast<const ulonglong2*>(&W[(8 * c + tx) * PAD + kk]);
#pragma unroll
            for (int r = 0; r < 4; r++)
#pragma unroll
                for (int c = 0; c < 4; c++) {
                    FMA2(acc[r][c], av[r].x, wv[c].x);
                    FMA2(acc[r][c], av[r].y, wv[c].y);
                }
        }
        __syncthreads();
    }

    // cell update: thread owns all 4 gates for d = d0+tx, b = 16r+ty
    const int dglob = d0 + tx;
#pragma unroll
    for (int r = 0; r < 4; r++) {
        float2 v;
        v = *reinterpret_cast<float2*>(&acc[r][0]); float gi = v.x + v.y;
        v = *reinterpret_cast<float2*>(&acc[r][1]); float gf = v.x + v.y;
        v = *reinterpret_cast<float2*>(&acc[r][2]); float gg = v.x + v.y;
        v = *reinterpret_cast<float2*>(&acc[r][3]); float go = v.x + v.y;

        float ii = sigf(gi);
        float ff = sigf(gf);
        float gv = tanhf(gg);
        float oo = sigf(go);

        const int  b  = 16 * r + ty;
        const long si = (long)b * Dc + dglob;
        float cn = ff * cst[si] + ii * gv;
        cst[si] = cn;
        float hn = oo * tanhf(cn);
        hnext[si] = hn;
        if (outp) outp[(long)b * Tc * Dc + dglob] = hn;
    }
}

// ---------------- persistent kernel ----------------
__global__ void __launch_bounds__(NT, 1)
lstm_persistent(const float* __restrict__ x,
                const float* __restrict__ Wih0, const float* __restrict__ Whh0,
                const float* __restrict__ Wih1, const float* __restrict__ Whh1,
                float* __restrict__ out)
{
    __shared__ __align__(16) float sA[2][64 * PAD];
    __shared__ __align__(16) float sW[2][32 * PAD];

    const int d0  = blockIdx.x * DPB;
    const int tid = threadIdx.x;

    // zero initial state (phase-0 h buffers + c) for this block's d slice
    for (int j = tid; j < Bc * DPB; j += NT) {
        int b = j & 63, dd = j >> 6;
        long si = (long)b * Dc + d0 + dd;
        g_h0[0][si] = 0.0f;
        g_h1[0][si] = 0.0f;
        g_c0[si]    = 0.0f;
        g_c1[si]    = 0.0f;
    }
    grid_barrier();

    for (int t = 0; t < Tc; t++) {
        const int p = t & 1;
        // layer 0: gates = x_t @ Wih0^T + h0_prev @ Whh0^T
        do_layer(x + (long)t * Dc, (long)Tc * Dc, g_h0[p],
                 Wih0, Whh0, g_c0, g_h0[p ^ 1], (float*)0, d0, sA, sW);
        grid_barrier();
        // layer 1: gates = h0_new @ Wih1^T + h1_prev @ Whh1^T ; h1 -> out
        do_layer(g_h0[p ^ 1], (long)Dc, g_h1[p],
                 Wih1, Whh1, g_c1, g_h1[p ^ 1], out + (long)t * Dc, d0, sA, sW);
        grid_barrier();
    }
}

// ---------------- harness entry ----------------
extern "C" void kernel_launch(void* const* d_in, const int* in_sizes, int n_in,
                              void* d_out, int out_size)
{
    const float* x    = (const float*)d_in[0];
    const float* Wih0 = (const float*)d_in[1];
    const float* Whh0 = (const float*)d_in[2];
    const float* Wih1 = (const float*)d_in[3];
    const float* Whh1 = (const float*)d_in[4];
    float* out        = (float*)d_out;
    (void)in_sizes; (void)n_in; (void)out_size;

    lstm_persistent<<<NB, NT>>>(x, Wih0, Whh0, Wih1, Whh1, out);
}